// round 12
// baseline (speedup 1.0000x reference)
#include <cuda_runtime.h>
#include <cuda_fp16.h>
#include <stdint.h>
#include <math.h>

// ---------------------------------------------------------------------------
// SimpleMamba via warp-level mma.sync fp16 GEMM (single product).
//   R12 = R10 mainloop (best: 549us) + fused tail:
//     - prep: single merged kernel (x->fp16, W->interleaved fp16 rows)
//     - gemm: persistent 148 CTAs, 512 thr, 4x4 warps (32x48), BK=64, 3-ring,
//             frag ping-pong, in-register gates, split scan -> (P,S)
//     - combine fused: last CTA (atomic counter) reduces 32 chunks + heads.
// ---------------------------------------------------------------------------

#define DM    1024
#define KD    1024
#define BM    128
#define BNC   64
#define BK    64
#define KTPT  16
#define NCHUNK 32
#define ASTR  66
#define NTILE 4096
#define NCTA  148

#define STAGE_BYTES 40960    // Ah 16K + Bh 24K
#define OFF_BH  16384
#define SCAN_OFF (3 * STAGE_BYTES)
#define SMEM_TOTAL (SCAN_OFF + 2 * BM * ASTR * 4)  // 190464

#define NTH 512

// ---------------- device scratch ----------------
__device__ __align__(128) __half g_Ah[32768u * 1024u];
__device__ __align__(128) __half g_Bh[3u * 1024u * 1024u];   // interleaved rows
__device__ float g_P[8 * NCHUNK * DM];
__device__ float g_S[8 * NCHUNK * DM];
__device__ unsigned int g_done = 0;

// ---------------- helpers ----------------
static __device__ __forceinline__ uint32_t smem_u32(const void* p) {
    uint32_t a;
    asm("{ .reg .u64 t; cvta.to.shared.u64 t, %1; cvt.u32.u64 %0, t; }" : "=r"(a) : "l"(p));
    return a;
}
static __device__ __forceinline__ uint32_t sw128(uint32_t o) { return o ^ ((o >> 3) & 0x70); }

static __device__ __forceinline__ void cp16(uint32_t dst, const void* src) {
    asm volatile("cp.async.cg.shared.global [%0], [%1], 16;" :: "r"(dst), "l"(src) : "memory");
}
static __device__ __forceinline__ void ldsm4(uint32_t* r, uint32_t addr) {
    asm volatile("ldmatrix.sync.aligned.m8n8.x4.shared.b16 {%0,%1,%2,%3}, [%4];"
        : "=r"(r[0]), "=r"(r[1]), "=r"(r[2]), "=r"(r[3]) : "r"(addr));
}
static __device__ __forceinline__ void mma_f16(float* c, const uint32_t* a,
                                               uint32_t b0, uint32_t b1) {
    asm volatile("mma.sync.aligned.m16n8k16.row.col.f32.f16.f16.f32 "
        "{%0,%1,%2,%3}, {%4,%5,%6,%7}, {%8,%9}, {%0,%1,%2,%3};"
        : "+f"(c[0]), "+f"(c[1]), "+f"(c[2]), "+f"(c[3])
        : "r"(a[0]), "r"(a[1]), "r"(a[2]), "r"(a[3]), "r"(b0), "r"(b1));
}

static __device__ __forceinline__ float softplus_f(float z) {
    return fmaxf(z, 0.0f) + __logf(1.0f + __expf(-fabsf(z)));
}

// ---------------- merged prep kernel ----------------
// blocks [0, 32768): x -> fp16    blocks [32768, 35840): W -> interleaved fp16
__global__ void __launch_bounds__(256)
prep_kernel(const float* __restrict__ x, const float* __restrict__ Wl,
            const float* __restrict__ Wd, const float* __restrict__ Wb) {
    const int tid = threadIdx.x;
    if (blockIdx.x < 32768) {
        size_t i = (size_t)blockIdx.x * 256 + tid;
        float4 v = ((const float4*)x)[i];
        __half2 H0, H1;
        H0.x = __float2half(v.x); H0.y = __float2half(v.y);
        H1.x = __float2half(v.z); H1.y = __float2half(v.w);
        ((__half2*)g_Ah)[2 * i] = H0;
        ((__half2*)g_Ah)[2 * i + 1] = H1;
    } else {
        const int bid = blockIdx.x - 32768;        // 0..3071
        const int mat = bid >> 10;                 // 0..2
        const int rem = bid & 1023;
        const int k0 = (rem >> 5) * 32;
        const int n0 = (rem & 31) * 32;
        const float* W = (mat == 0) ? Wl : (mat == 1) ? Wd : Wb;
        __shared__ float ts[32][33];
        const int tx = tid & 31, ty = tid >> 5;    // 32 x 8
#pragma unroll
        for (int i = 0; i < 4; i++) {
            int k = ty + i * 8;
            ts[k][tx] = W[(size_t)(k0 + k) * DM + n0 + tx];
        }
        __syncthreads();
#pragma unroll
        for (int i = 0; i < 4; i++) {
            int n = n0 + ty + i * 8;
            int row = (n >> 4) * 48 + mat * 16 + (n & 15);
            g_Bh[(size_t)row * KD + k0 + tx] = __float2half(ts[tx][ty + i * 8]);
        }
    }
}

// ---------------- GEMM + scan + fused combine (persistent) ----------------
static __device__ __forceinline__ void load_stage(int s, int cta, int tid, uint32_t sb) {
    const int tile = cta + NCTA * (s >> 4);
    const int kt = s & 15;
    const int R = (tile >> 4) * BM;
    const int Crow = (tile & 15) * 192;
    const uint32_t st = sb + (s % 3) * STAGE_BYTES;
#pragma unroll
    for (int i = 0; i < 2; i++) {
        int c = i * NTH + tid;
        int row = c >> 3, q = c & 7;
        size_t g = ((size_t)(R + row) << 10) + kt * BK + q * 8;
        cp16(st + sw128((uint32_t)(row * 128 + q * 16)), g_Ah + g);
    }
#pragma unroll
    for (int i = 0; i < 3; i++) {
        int c = i * NTH + tid;
        int row = c >> 3, q = c & 7;
        size_t g = ((size_t)(Crow + row) << 10) + kt * BK + q * 8;
        cp16(st + OFF_BH + sw128((uint32_t)(row * 128 + q * 16)), g_Bh + g);
    }
    asm volatile("cp.async.commit_group;" ::: "memory");
}

static __device__ __forceinline__ void frag_load(uint32_t A[2][4], uint32_t B[3][4],
                                                 uint32_t st, int kb,
                                                 int a_row_l, int a_cb,
                                                 int b_row_l, int b_cb) {
#pragma unroll
    for (int mt = 0; mt < 2; mt++)
        ldsm4(A[mt], st + sw128((uint32_t)((a_row_l + mt * 16) * 128 + kb + a_cb)));
#pragma unroll
    for (int nt = 0; nt < 3; nt++)
        ldsm4(B[nt], st + OFF_BH + sw128((uint32_t)((b_row_l + nt * 16) * 128 + kb + b_cb)));
}

static __device__ __forceinline__ void do_mma(float acc[2][6][4],
                                              uint32_t A[2][4], uint32_t B[3][4]) {
#pragma unroll
    for (int mt = 0; mt < 2; mt++)
#pragma unroll
        for (int nt = 0; nt < 3; nt++) {
            mma_f16(acc[mt][2 * nt],     A[mt], B[nt][0], B[nt][1]);
            mma_f16(acc[mt][2 * nt + 1], A[mt], B[nt][2], B[nt][3]);
        }
}

__global__ void __launch_bounds__(NTH)
mamba_gemm_mma(const float* __restrict__ pbl, const float* __restrict__ pbd,
               const float* __restrict__ pbb,
               const float* __restrict__ Wp, const float* __restrict__ bp,
               const float* __restrict__ Wa, const float* __restrict__ ba,
               float* __restrict__ out) {
    extern __shared__ char smem[];
    const uint32_t sb = smem_u32(smem);
    const int tid = threadIdx.x;
    const int warp = tid >> 5;
    const int lane = tid & 31;
    const int cta = blockIdx.x;
    const int wm = warp >> 2;
    const int wn = warp & 3;

    const int ntiles = (NTILE - cta + NCTA - 1) / NCTA;
    const int G = ntiles * KTPT;

    float* SA = (float*)(smem + SCAN_OFF);
    float* SD = SA + BM * ASTR;
    __shared__ float sP[2][BNC], sS[2][BNC];

    float acc[2][6][4];
#pragma unroll
    for (int i = 0; i < 2; i++)
#pragma unroll
        for (int j = 0; j < 6; j++)
#pragma unroll
            for (int k = 0; k < 4; k++) acc[i][j][k] = 0.0f;

    const int a_row_l = wm * 32 + (lane & 15);
    const int a_cb = (lane >> 4) * 16;
    const int b_row_l = wn * 48 + ((lane >> 4) & 1) * 8 + (lane & 7);
    const int b_cb = ((lane >> 3) & 1) * 16;
    const int q2 = 2 * (lane & 3);

    uint32_t Af[2][2][4], Bf[2][3][4];

    load_stage(0, cta, tid, sb);
    load_stage(1, cta, tid, sb);
    asm volatile("cp.async.wait_group 1;" ::: "memory");
    __syncthreads();
    frag_load(Af[0], Bf[0], sb, 0, a_row_l, a_cb, b_row_l, b_cb);

    for (int s = 0; s < G; s++) {
        const uint32_t st = sb + (s % 3) * STAGE_BYTES;
        if (s + 2 < G) load_stage(s + 2, cta, tid, sb);
#pragma unroll
        for (int ks = 0; ks < 4; ks++) {
            const int cur = ks & 1, nxt = cur ^ 1;
            if (ks < 3) {
                frag_load(Af[nxt], Bf[nxt], st, (ks + 1) * 32,
                          a_row_l, a_cb, b_row_l, b_cb);
            } else if (s + 1 < G) {
                if (s + 2 < G)
                    asm volatile("cp.async.wait_group 1;" ::: "memory");
                else
                    asm volatile("cp.async.wait_group 0;" ::: "memory");
                __syncthreads();
                frag_load(Af[nxt], Bf[nxt], sb + ((s + 1) % 3) * STAGE_BYTES, 0,
                          a_row_l, a_cb, b_row_l, b_cb);
            }
            do_mma(acc, Af[cur], Bf[cur]);
        }

        if ((s & (KTPT - 1)) == KTPT - 1) {
            const int tile = cta + NCTA * (s >> 4);
            const int R = (tile >> 4) * BM;
            const int C = (tile & 15) * BNC;

            {
                float bl_[2][2], bd_[2][2], bb_[2][2];
#pragma unroll
                for (int g = 0; g < 2; g++)
#pragma unroll
                    for (int e = 0; e < 2; e++) {
                        const int gc = C + wn * 16 + g * 8 + q2 + e;
                        bl_[g][e] = __ldg(pbl + gc);
                        bd_[g][e] = __ldg(pbd + gc);
                        bb_[g][e] = __ldg(pbb + gc);
                    }
#pragma unroll
                for (int mt = 0; mt < 2; mt++)
#pragma unroll
                    for (int h = 0; h < 2; h++) {
                        const int row = wm * 32 + mt * 16 + (lane >> 2) + 8 * h;
#pragma unroll
                        for (int g = 0; g < 2; g++) {
                            float a0, a1, d0, d1;
#pragma unroll
                            for (int e = 0; e < 2; e++) {
                                float lam = softplus_f(acc[mt][g][2 * h + e]     + bl_[g][e]);
                                float de  = softplus_f(acc[mt][2 + g][2 * h + e] + bd_[g][e]);
                                float u   = acc[mt][4 + g][2 * h + e] + bb_[g][e];
                                float al  = __expf(-de * lam);
                                float dr  = de * u;
                                if (e == 0) { a0 = al; d0 = dr; } else { a1 = al; d1 = dr; }
                            }
                            const int ch = wn * 16 + g * 8 + q2;
                            *(float2*)&SA[row * ASTR + ch] = make_float2(a0, a1);
                            *(float2*)&SD[row * ASTR + ch] = make_float2(d0, d1);
                        }
                    }
            }
            __syncthreads();

            if (tid < 2 * BNC) {
                const int ch = tid & 63;
                const int hf = tid >> 6;
                float sc = 0.0f, P = 1.0f;
                const int t0 = hf * 64;
#pragma unroll 8
                for (int t = t0; t < t0 + 64; t++) {
                    float a = SA[t * ASTR + ch];
                    float d = SD[t * ASTR + ch];
                    sc = fmaf(a, sc, d);
                    P *= a;
                }
                sP[hf][ch] = P;
                sS[hf][ch] = sc;
            }
            __syncthreads();
            if (tid < BNC) {
                const float P = sP[0][tid] * sP[1][tid];
                const float sc = fmaf(sP[1][tid], sS[0][tid], sS[1][tid]);
                const int bidx = R >> 12;
                const int chunk = (R >> 7) & 31;
                const int idx = ((bidx * NCHUNK + chunk) << 10) + C + tid;
                g_P[idx] = P;
                g_S[idx] = sc;
            }

#pragma unroll
            for (int i = 0; i < 2; i++)
#pragma unroll
                for (int j = 0; j < 6; j++)
#pragma unroll
                    for (int k = 0; k < 4; k++) acc[i][j][k] = 0.0f;
            __syncthreads();
        }
    }

    // ---- fused combine: last CTA to finish reduces chunks + heads ----
    __threadfence();
    __shared__ int is_last;
    if (tid == 0) is_last = (atomicAdd(&g_done, 1u) == NCTA - 1) ? 1 : 0;
    __syncthreads();
    if (is_last) {
        __threadfence();
        __shared__ float r0[16], r1[16], r2[16];
        const int ch0 = tid * 2;
        for (int b = 0; b < 8; b++) {
            float v0 = 0.0f, v1 = 0.0f, v2 = 0.0f;
#pragma unroll
            for (int cc = 0; cc < 2; cc++) {
                const int d = ch0 + cc;
                float sc = 0.0f;
#pragma unroll
                for (int c = 0; c < NCHUNK; c++) {
                    const int idx = ((b * NCHUNK + c) << 10) + d;
                    sc = fmaf(g_P[idx], sc, g_S[idx]);
                }
                v0 = fmaf(sc, Wp[2 * d], v0);
                v1 = fmaf(sc, Wp[2 * d + 1], v1);
                v2 = fmaf(sc, Wa[d], v2);
            }
#pragma unroll
            for (int o = 16; o > 0; o >>= 1) {
                v0 += __shfl_xor_sync(0xffffffffu, v0, o);
                v1 += __shfl_xor_sync(0xffffffffu, v1, o);
                v2 += __shfl_xor_sync(0xffffffffu, v2, o);
            }
            if (lane == 0) { r0[warp] = v0; r1[warp] = v1; r2[warp] = v2; }
            __syncthreads();
            if (warp == 0) {
                v0 = (lane < 16) ? r0[lane] : 0.0f;
                v1 = (lane < 16) ? r1[lane] : 0.0f;
                v2 = (lane < 16) ? r2[lane] : 0.0f;
#pragma unroll
                for (int o = 8; o > 0; o >>= 1) {
                    v0 += __shfl_xor_sync(0xffffffffu, v0, o);
                    v1 += __shfl_xor_sync(0xffffffffu, v1, o);
                    v2 += __shfl_xor_sync(0xffffffffu, v2, o);
                }
                if (lane == 0) {
                    out[2 * b]     = v0 + bp[0];
                    out[2 * b + 1] = v1 + bp[1];
                    out[16 + b]    = v2 + ba[0];
                }
            }
            __syncthreads();
        }
        if (tid == 0) g_done = 0;   // reset for next graph replay
    }
}

extern "C" void kernel_launch(void* const* d_in, const int* in_sizes, int n_in,
                              void* d_out, int out_size)
{
    const float* x  = (const float*)d_in[0];
    const float* Wl = (const float*)d_in[1];
    const float* bl = (const float*)d_in[2];
    const float* Wd = (const float*)d_in[3];
    const float* bd = (const float*)d_in[4];
    const float* Wb = (const float*)d_in[5];
    const float* bb = (const float*)d_in[6];
    const float* Wp = (const float*)d_in[7];
    const float* bp = (const float*)d_in[8];
    const float* Wa = (const float*)d_in[9];
    const float* ba = (const float*)d_in[10];
    float* out = (float*)d_out;

    cudaFuncSetAttribute(mamba_gemm_mma,
                         cudaFuncAttributeMaxDynamicSharedMemorySize, SMEM_TOTAL);

    prep_kernel<<<32768 + 3072, 256>>>(x, Wl, Wd, Wb);
    mamba_gemm_mma<<<NCTA, NTH, SMEM_TOTAL>>>(bl, bd, bb, Wp, bp, Wa, ba, out);
}

// round 14
// speedup vs baseline: 1.2956x; 1.2956x over previous
#include <cuda_runtime.h>
#include <cuda_fp16.h>
#include <stdint.h>
#include <math.h>

// ---------------------------------------------------------------------------
// SimpleMamba via warp-level mma.sync fp16 GEMM (single product).
//   R14 = R13 with the swizzle-hoist bug FIXED: kb (bits 5-6) is disjoint
//   from the base's low bits (cb = bit 4), so base+kb == base^kb and
//   sw128(base^kb) == sw128(base)^kb  -> addr = st + (off ^ kb). XOR not ADD.
//   Persistent 148 CTAs, 512 thr, 4x4 warps (32x48), BK=64, 3-ring, ping-pong.
// ---------------------------------------------------------------------------

#define DM    1024
#define KD    1024
#define BM    128
#define BNC   64
#define BK    64
#define KTPT  16
#define NCHUNK 32
#define ASTR  66
#define NTILE 4096
#define NCTA  148

#define STAGE_BYTES 40960    // Ah 16K + Bh 24K
#define OFF_BH  16384
#define SCAN_OFF (3 * STAGE_BYTES)
#define SMEM_TOTAL (SCAN_OFF + 2 * BM * ASTR * 4)  // 190464

#define NTH 512

// ---------------- device scratch ----------------
__device__ __align__(128) __half g_Ah[32768u * 1024u];
__device__ __align__(128) __half g_Bh[3u * 1024u * 1024u];   // interleaved rows
__device__ float g_P[8 * NCHUNK * DM];
__device__ float g_S[8 * NCHUNK * DM];

// ---------------- helpers ----------------
static __device__ __forceinline__ uint32_t smem_u32(const void* p) {
    uint32_t a;
    asm("{ .reg .u64 t; cvta.to.shared.u64 t, %1; cvt.u32.u64 %0, t; }" : "=r"(a) : "l"(p));
    return a;
}
static __device__ __forceinline__ uint32_t sw128(uint32_t o) { return o ^ ((o >> 3) & 0x70); }

static __device__ __forceinline__ void cp16(uint32_t dst, const void* src) {
    asm volatile("cp.async.cg.shared.global [%0], [%1], 16;" :: "r"(dst), "l"(src) : "memory");
}
static __device__ __forceinline__ void ldsm4(uint32_t* r, uint32_t addr) {
    asm volatile("ldmatrix.sync.aligned.m8n8.x4.shared.b16 {%0,%1,%2,%3}, [%4];"
        : "=r"(r[0]), "=r"(r[1]), "=r"(r[2]), "=r"(r[3]) : "r"(addr));
}
static __device__ __forceinline__ void mma_f16(float* c, const uint32_t* a,
                                               uint32_t b0, uint32_t b1) {
    asm volatile("mma.sync.aligned.m16n8k16.row.col.f32.f16.f16.f32 "
        "{%0,%1,%2,%3}, {%4,%5,%6,%7}, {%8,%9}, {%0,%1,%2,%3};"
        : "+f"(c[0]), "+f"(c[1]), "+f"(c[2]), "+f"(c[3])
        : "r"(a[0]), "r"(a[1]), "r"(a[2]), "r"(a[3]), "r"(b0), "r"(b1));
}

static __device__ __forceinline__ float softplus_f(float z) {
    return fmaxf(z, 0.0f) + __logf(1.0f + __expf(-fabsf(z)));
}

// ---------------- merged prep kernel ----------------
__global__ void __launch_bounds__(256)
prep_kernel(const float* __restrict__ x, const float* __restrict__ Wl,
            const float* __restrict__ Wd, const float* __restrict__ Wb) {
    const int tid = threadIdx.x;
    if (blockIdx.x < 32768) {
        size_t i = (size_t)blockIdx.x * 256 + tid;
        float4 v = ((const float4*)x)[i];
        __half2 H0, H1;
        H0.x = __float2half(v.x); H0.y = __float2half(v.y);
        H1.x = __float2half(v.z); H1.y = __float2half(v.w);
        ((__half2*)g_Ah)[2 * i] = H0;
        ((__half2*)g_Ah)[2 * i + 1] = H1;
    } else {
        const int bid = blockIdx.x - 32768;        // 0..3071
        const int mat = bid >> 10;
        const int rem = bid & 1023;
        const int k0 = (rem >> 5) * 32;
        const int n0 = (rem & 31) * 32;
        const float* W = (mat == 0) ? Wl : (mat == 1) ? Wd : Wb;
        __shared__ float ts[32][33];
        const int tx = tid & 31, ty = tid >> 5;
#pragma unroll
        for (int i = 0; i < 4; i++) {
            int k = ty + i * 8;
            ts[k][tx] = W[(size_t)(k0 + k) * DM + n0 + tx];
        }
        __syncthreads();
#pragma unroll
        for (int i = 0; i < 4; i++) {
            int n = n0 + ty + i * 8;
            int row = (n >> 4) * 48 + mat * 16 + (n & 15);
            g_Bh[(size_t)row * KD + k0 + tx] = __float2half(ts[tx][ty + i * 8]);
        }
    }
}

// ---------------- GEMM + scan (persistent) ----------------
static __device__ __forceinline__ void load_stage(int s, int cta, int tid, uint32_t sb) {
    const int tile = cta + NCTA * (s >> 4);
    const int kt = s & 15;
    const int R = (tile >> 4) * BM;
    const int Crow = (tile & 15) * 192;
    const uint32_t st = sb + (s % 3) * STAGE_BYTES;
#pragma unroll
    for (int i = 0; i < 2; i++) {
        int c = i * NTH + tid;
        int row = c >> 3, q = c & 7;
        size_t g = ((size_t)(R + row) << 10) + kt * BK + q * 8;
        cp16(st + sw128((uint32_t)(row * 128 + q * 16)), g_Ah + g);
    }
#pragma unroll
    for (int i = 0; i < 3; i++) {
        int c = i * NTH + tid;
        int row = c >> 3, q = c & 7;
        size_t g = ((size_t)(Crow + row) << 10) + kt * BK + q * 8;
        cp16(st + OFF_BH + sw128((uint32_t)(row * 128 + q * 16)), g_Bh + g);
    }
    asm volatile("cp.async.commit_group;" ::: "memory");
}

// precomputed swizzled base offsets; addr = st + (base ^ kb), kb in {0,32,64,96}
// valid because kb bits (5-6) are disjoint from cb bit (4) in the base offset.
static __device__ __forceinline__ void frag_load(uint32_t A[2][4], uint32_t B[3][4],
                                                 uint32_t st, uint32_t kb,
                                                 const uint32_t aoff[2],
                                                 const uint32_t boff[3]) {
#pragma unroll
    for (int mt = 0; mt < 2; mt++)
        ldsm4(A[mt], st + (aoff[mt] ^ kb));
#pragma unroll
    for (int nt = 0; nt < 3; nt++)
        ldsm4(B[nt], st + (boff[nt] ^ kb));
}

static __device__ __forceinline__ void do_mma(float acc[2][6][4],
                                              uint32_t A[2][4], uint32_t B[3][4]) {
#pragma unroll
    for (int mt = 0; mt < 2; mt++)
#pragma unroll
        for (int nt = 0; nt < 3; nt++) {
            mma_f16(acc[mt][2 * nt],     A[mt], B[nt][0], B[nt][1]);
            mma_f16(acc[mt][2 * nt + 1], A[mt], B[nt][2], B[nt][3]);
        }
}

__global__ void __launch_bounds__(NTH)
mamba_gemm_mma(const float* __restrict__ pbl, const float* __restrict__ pbd,
               const float* __restrict__ pbb) {
    extern __shared__ char smem[];
    const uint32_t sb = smem_u32(smem);
    const int tid = threadIdx.x;
    const int warp = tid >> 5;
    const int lane = tid & 31;
    const int cta = blockIdx.x;
    const int wm = warp >> 2;
    const int wn = warp & 3;

    const int ntiles = (NTILE - cta + NCTA - 1) / NCTA;
    const int G = ntiles * KTPT;

    float* SA = (float*)(smem + SCAN_OFF);
    float* SD = SA + BM * ASTR;
    __shared__ float sP[2][BNC], sS[2][BNC];

    float acc[2][6][4];
#pragma unroll
    for (int i = 0; i < 2; i++)
#pragma unroll
        for (int j = 0; j < 6; j++)
#pragma unroll
            for (int k = 0; k < 4; k++) acc[i][j][k] = 0.0f;

    const int a_row_l = wm * 32 + (lane & 15);
    const int a_cb = (lane >> 4) * 16;
    const int b_row_l = wn * 48 + ((lane >> 4) & 1) * 8 + (lane & 7);
    const int b_cb = ((lane >> 3) & 1) * 16;
    const int q2 = 2 * (lane & 3);

    // loop-invariant swizzled base offsets; per-slice addr = base ^ kb
    uint32_t aoff[2], boff[3];
#pragma unroll
    for (int mt = 0; mt < 2; mt++)
        aoff[mt] = sw128((uint32_t)((a_row_l + mt * 16) * 128 + a_cb));
#pragma unroll
    for (int nt = 0; nt < 3; nt++)
        boff[nt] = OFF_BH + sw128((uint32_t)((b_row_l + nt * 16) * 128 + b_cb));

    uint32_t Af[2][2][4], Bf[2][3][4];

    load_stage(0, cta, tid, sb);
    load_stage(1, cta, tid, sb);
    asm volatile("cp.async.wait_group 1;" ::: "memory");
    __syncthreads();
    frag_load(Af[0], Bf[0], sb, 0, aoff, boff);

    for (int s = 0; s < G; s++) {
        const uint32_t st = sb + (s % 3) * STAGE_BYTES;
        if (s + 2 < G) load_stage(s + 2, cta, tid, sb);
#pragma unroll
        for (int ks = 0; ks < 4; ks++) {
            const int cur = ks & 1, nxt = cur ^ 1;
            if (ks < 3) {
                frag_load(Af[nxt], Bf[nxt], st, (uint32_t)((ks + 1) * 32), aoff, boff);
            } else if (s + 1 < G) {
                if (s + 2 < G)
                    asm volatile("cp.async.wait_group 1;" ::: "memory");
                else
                    asm volatile("cp.async.wait_group 0;" ::: "memory");
                __syncthreads();
                frag_load(Af[nxt], Bf[nxt], sb + ((s + 1) % 3) * STAGE_BYTES, 0,
                          aoff, boff);
            }
            do_mma(acc, Af[cur], Bf[cur]);
        }

        if ((s & (KTPT - 1)) == KTPT - 1) {
            const int tile = cta + NCTA * (s >> 4);
            const int R = (tile >> 4) * BM;
            const int C = (tile & 15) * BNC;

            {
                float bl_[2][2], bd_[2][2], bb_[2][2];
#pragma unroll
                for (int g = 0; g < 2; g++)
#pragma unroll
                    for (int e = 0; e < 2; e++) {
                        const int gc = C + wn * 16 + g * 8 + q2 + e;
                        bl_[g][e] = __ldg(pbl + gc);
                        bd_[g][e] = __ldg(pbd + gc);
                        bb_[g][e] = __ldg(pbb + gc);
                    }
#pragma unroll
                for (int mt = 0; mt < 2; mt++)
#pragma unroll
                    for (int h = 0; h < 2; h++) {
                        const int row = wm * 32 + mt * 16 + (lane >> 2) + 8 * h;
#pragma unroll
                        for (int g = 0; g < 2; g++) {
                            float a0, a1, d0, d1;
#pragma unroll
                            for (int e = 0; e < 2; e++) {
                                float lam = softplus_f(acc[mt][g][2 * h + e]     + bl_[g][e]);
                                float de  = softplus_f(acc[mt][2 + g][2 * h + e] + bd_[g][e]);
                                float u   = acc[mt][4 + g][2 * h + e] + bb_[g][e];
                                float al  = __expf(-de * lam);
                                float dr  = de * u;
                                if (e == 0) { a0 = al; d0 = dr; } else { a1 = al; d1 = dr; }
                            }
                            const int ch = wn * 16 + g * 8 + q2;
                            *(float2*)&SA[row * ASTR + ch] = make_float2(a0, a1);
                            *(float2*)&SD[row * ASTR + ch] = make_float2(d0, d1);
                        }
                    }
            }
            __syncthreads();

            if (tid < 2 * BNC) {
                const int ch = tid & 63;
                const int hf = tid >> 6;
                float sc = 0.0f, P = 1.0f;
                const int t0 = hf * 64;
#pragma unroll 8
                for (int t = t0; t < t0 + 64; t++) {
                    float a = SA[t * ASTR + ch];
                    float d = SD[t * ASTR + ch];
                    sc = fmaf(a, sc, d);
                    P *= a;
                }
                sP[hf][ch] = P;
                sS[hf][ch] = sc;
            }
            __syncthreads();
            if (tid < BNC) {
                const float P = sP[0][tid] * sP[1][tid];
                const float sc = fmaf(sP[1][tid], sS[0][tid], sS[1][tid]);
                const int bidx = R >> 12;
                const int chunk = (R >> 7) & 31;
                const int idx = ((bidx * NCHUNK + chunk) << 10) + C + tid;
                g_P[idx] = P;
                g_S[idx] = sc;
            }

#pragma unroll
            for (int i = 0; i < 2; i++)
#pragma unroll
                for (int j = 0; j < 6; j++)
#pragma unroll
                    for (int k = 0; k < 4; k++) acc[i][j][k] = 0.0f;
            __syncthreads();
        }
    }
}

// ---------------- combine chunks + head projections ----------------
__global__ void __launch_bounds__(1024)
combine_kernel(const float* __restrict__ W_par, const float* __restrict__ b_par,
               const float* __restrict__ W_add, const float* __restrict__ b_add,
               float* __restrict__ out)
{
    const int b = blockIdx.x;
    const int d = threadIdx.x;

    float s = 0.0f;
#pragma unroll
    for (int c = 0; c < NCHUNK; c++) {
        const int idx = ((b * NCHUNK + c) << 10) + d;
        s = fmaf(g_P[idx], s, g_S[idx]);
    }

    float v0 = s * W_par[2 * d];
    float v1 = s * W_par[2 * d + 1];
    float v2 = s * W_add[d];

#pragma unroll
    for (int o = 16; o > 0; o >>= 1) {
        v0 += __shfl_xor_sync(0xffffffffu, v0, o);
        v1 += __shfl_xor_sync(0xffffffffu, v1, o);
        v2 += __shfl_xor_sync(0xffffffffu, v2, o);
    }

    __shared__ float r0[32], r1[32], r2[32];
    const int lane = d & 31, wid = d >> 5;
    if (lane == 0) { r0[wid] = v0; r1[wid] = v1; r2[wid] = v2; }
    __syncthreads();
    if (wid == 0) {
        v0 = r0[lane]; v1 = r1[lane]; v2 = r2[lane];
#pragma unroll
        for (int o = 16; o > 0; o >>= 1) {
            v0 += __shfl_xor_sync(0xffffffffu, v0, o);
            v1 += __shfl_xor_sync(0xffffffffu, v1, o);
            v2 += __shfl_xor_sync(0xffffffffu, v2, o);
        }
        if (lane == 0) {
            out[2 * b]     = v0 + b_par[0];
            out[2 * b + 1] = v1 + b_par[1];
            out[16 + b]    = v2 + b_add[0];
        }
    }
}

extern "C" void kernel_launch(void* const* d_in, const int* in_sizes, int n_in,
                              void* d_out, int out_size)
{
    const float* x  = (const float*)d_in[0];
    const float* Wl = (const float*)d_in[1];
    const float* bl = (const float*)d_in[2];
    const float* Wd = (const float*)d_in[3];
    const float* bd = (const float*)d_in[4];
    const float* Wb = (const float*)d_in[5];
    const float* bb = (const float*)d_in[6];
    const float* Wp = (const float*)d_in[7];
    const float* bp = (const float*)d_in[8];
    const float* Wa = (const float*)d_in[9];
    const float* ba = (const float*)d_in[10];
    float* out = (float*)d_out;

    cudaFuncSetAttribute(mamba_gemm_mma,
                         cudaFuncAttributeMaxDynamicSharedMemorySize, SMEM_TOTAL);

    prep_kernel<<<32768 + 3072, 256>>>(x, Wl, Wd, Wb);
    mamba_gemm_mma<<<NCTA, NTH, SMEM_TOTAL>>>(bl, bd, bb);
    combine_kernel<<<8, 1024>>>(Wp, bp, Wa, ba, out);
}

// round 15
// speedup vs baseline: 1.3848x; 1.0689x over previous
#include <cuda_runtime.h>
#include <cuda_fp16.h>
#include <stdint.h>
#include <math.h>

// ---------------------------------------------------------------------------
// SimpleMamba via warp-level mma.sync fp16 GEMM (single product).
//   R15 = R10 gemm/combine VERBATIM (best: 548.7us) + vectorized merged prep:
//   each prep thread converts 8 floats -> one 16B uint4 store (was 2x4B).
//   Persistent 148 CTAs, 512 thr, 4x4 warps (32x48), BK=64, 3-ring, ping-pong,
//   in-register gates, split scan -> (P,S); separate 8us combine kernel.
// ---------------------------------------------------------------------------

#define DM    1024
#define KD    1024
#define BM    128
#define BNC   64
#define BK    64
#define KTPT  16
#define NCHUNK 32
#define ASTR  66
#define NTILE 4096
#define NCTA  148

#define STAGE_BYTES 40960    // Ah 16K + Bh 24K
#define OFF_BH  16384
#define SCAN_OFF (3 * STAGE_BYTES)
#define SMEM_TOTAL (SCAN_OFF + 2 * BM * ASTR * 4)  // 190464

#define NTH 512

// ---------------- device scratch ----------------
__device__ __align__(128) __half g_Ah[32768u * 1024u];
__device__ __align__(128) __half g_Bh[3u * 1024u * 1024u];   // interleaved rows
__device__ float g_P[8 * NCHUNK * DM];
__device__ float g_S[8 * NCHUNK * DM];

// ---------------- helpers ----------------
static __device__ __forceinline__ uint32_t smem_u32(const void* p) {
    uint32_t a;
    asm("{ .reg .u64 t; cvta.to.shared.u64 t, %1; cvt.u32.u64 %0, t; }" : "=r"(a) : "l"(p));
    return a;
}
static __device__ __forceinline__ uint32_t sw128(uint32_t o) { return o ^ ((o >> 3) & 0x70); }

static __device__ __forceinline__ void cp16(uint32_t dst, const void* src) {
    asm volatile("cp.async.cg.shared.global [%0], [%1], 16;" :: "r"(dst), "l"(src) : "memory");
}
static __device__ __forceinline__ void ldsm4(uint32_t* r, uint32_t addr) {
    asm volatile("ldmatrix.sync.aligned.m8n8.x4.shared.b16 {%0,%1,%2,%3}, [%4];"
        : "=r"(r[0]), "=r"(r[1]), "=r"(r[2]), "=r"(r[3]) : "r"(addr));
}
static __device__ __forceinline__ void mma_f16(float* c, const uint32_t* a,
                                               uint32_t b0, uint32_t b1) {
    asm volatile("mma.sync.aligned.m16n8k16.row.col.f32.f16.f16.f32 "
        "{%0,%1,%2,%3}, {%4,%5,%6,%7}, {%8,%9}, {%0,%1,%2,%3};"
        : "+f"(c[0]), "+f"(c[1]), "+f"(c[2]), "+f"(c[3])
        : "r"(a[0]), "r"(a[1]), "r"(a[2]), "r"(a[3]), "r"(b0), "r"(b1));
}

static __device__ __forceinline__ float softplus_f(float z) {
    return fmaxf(z, 0.0f) + __logf(1.0f + __expf(-fabsf(z)));
}

// ---------------- merged prep kernel (vectorized) ----------------
// blocks [0, 16384): x -> fp16 (8 floats/thread, one 16B store)
// blocks [16384, 19456): W -> interleaved fp16 rows
__global__ void __launch_bounds__(256)
prep_kernel(const float* __restrict__ x, const float* __restrict__ Wl,
            const float* __restrict__ Wd, const float* __restrict__ Wb) {
    const int tid = threadIdx.x;
    if (blockIdx.x < 16384) {
        size_t i = (size_t)blockIdx.x * 256 + tid;   // 8-float group index
        float4 v0 = ((const float4*)x)[2 * i];
        float4 v1 = ((const float4*)x)[2 * i + 1];
        __half2 h[4];
        h[0] = __floats2half2_rn(v0.x, v0.y);
        h[1] = __floats2half2_rn(v0.z, v0.w);
        h[2] = __floats2half2_rn(v1.x, v1.y);
        h[3] = __floats2half2_rn(v1.z, v1.w);
        ((uint4*)g_Ah)[i] = *(const uint4*)h;
    } else {
        const int bid = blockIdx.x - 16384;        // 0..3071
        const int mat = bid >> 10;
        const int rem = bid & 1023;
        const int k0 = (rem >> 5) * 32;
        const int n0 = (rem & 31) * 32;
        const float* W = (mat == 0) ? Wl : (mat == 1) ? Wd : Wb;
        __shared__ float ts[32][33];
        const int tx = tid & 31, ty = tid >> 5;
#pragma unroll
        for (int i = 0; i < 4; i++) {
            int k = ty + i * 8;
            ts[k][tx] = W[(size_t)(k0 + k) * DM + n0 + tx];
        }
        __syncthreads();
#pragma unroll
        for (int i = 0; i < 4; i++) {
            int n = n0 + ty + i * 8;
            int row = (n >> 4) * 48 + mat * 16 + (n & 15);
            g_Bh[(size_t)row * KD + k0 + tx] = __float2half(ts[tx][ty + i * 8]);
        }
    }
}

// ---------------- GEMM + scan (persistent, R10 verbatim) ----------------
static __device__ __forceinline__ void load_stage(int s, int cta, int tid, uint32_t sb) {
    const int tile = cta + NCTA * (s >> 4);
    const int kt = s & 15;
    const int R = (tile >> 4) * BM;
    const int Crow = (tile & 15) * 192;
    const uint32_t st = sb + (s % 3) * STAGE_BYTES;
#pragma unroll
    for (int i = 0; i < 2; i++) {
        int c = i * NTH + tid;
        int row = c >> 3, q = c & 7;
        size_t g = ((size_t)(R + row) << 10) + kt * BK + q * 8;
        cp16(st + sw128((uint32_t)(row * 128 + q * 16)), g_Ah + g);
    }
#pragma unroll
    for (int i = 0; i < 3; i++) {
        int c = i * NTH + tid;
        int row = c >> 3, q = c & 7;
        size_t g = ((size_t)(Crow + row) << 10) + kt * BK + q * 8;
        cp16(st + OFF_BH + sw128((uint32_t)(row * 128 + q * 16)), g_Bh + g);
    }
    asm volatile("cp.async.commit_group;" ::: "memory");
}

static __device__ __forceinline__ void frag_load(uint32_t A[2][4], uint32_t B[3][4],
                                                 uint32_t st, int kb,
                                                 int a_row_l, int a_cb,
                                                 int b_row_l, int b_cb) {
#pragma unroll
    for (int mt = 0; mt < 2; mt++)
        ldsm4(A[mt], st + sw128((uint32_t)((a_row_l + mt * 16) * 128 + kb + a_cb)));
#pragma unroll
    for (int nt = 0; nt < 3; nt++)
        ldsm4(B[nt], st + OFF_BH + sw128((uint32_t)((b_row_l + nt * 16) * 128 + kb + b_cb)));
}

static __device__ __forceinline__ void do_mma(float acc[2][6][4],
                                              uint32_t A[2][4], uint32_t B[3][4]) {
#pragma unroll
    for (int mt = 0; mt < 2; mt++)
#pragma unroll
        for (int nt = 0; nt < 3; nt++) {
            mma_f16(acc[mt][2 * nt],     A[mt], B[nt][0], B[nt][1]);
            mma_f16(acc[mt][2 * nt + 1], A[mt], B[nt][2], B[nt][3]);
        }
}

__global__ void __launch_bounds__(NTH)
mamba_gemm_mma(const float* __restrict__ pbl, const float* __restrict__ pbd,
               const float* __restrict__ pbb) {
    extern __shared__ char smem[];
    const uint32_t sb = smem_u32(smem);
    const int tid = threadIdx.x;
    const int warp = tid >> 5;
    const int lane = tid & 31;
    const int cta = blockIdx.x;
    const int wm = warp >> 2;
    const int wn = warp & 3;

    const int ntiles = (NTILE - cta + NCTA - 1) / NCTA;
    const int G = ntiles * KTPT;

    float* SA = (float*)(smem + SCAN_OFF);
    float* SD = SA + BM * ASTR;
    __shared__ float sP[2][BNC], sS[2][BNC];

    float acc[2][6][4];
#pragma unroll
    for (int i = 0; i < 2; i++)
#pragma unroll
        for (int j = 0; j < 6; j++)
#pragma unroll
            for (int k = 0; k < 4; k++) acc[i][j][k] = 0.0f;

    const int a_row_l = wm * 32 + (lane & 15);
    const int a_cb = (lane >> 4) * 16;
    const int b_row_l = wn * 48 + ((lane >> 4) & 1) * 8 + (lane & 7);
    const int b_cb = ((lane >> 3) & 1) * 16;
    const int q2 = 2 * (lane & 3);

    uint32_t Af[2][2][4], Bf[2][3][4];

    load_stage(0, cta, tid, sb);
    load_stage(1, cta, tid, sb);
    asm volatile("cp.async.wait_group 1;" ::: "memory");
    __syncthreads();
    frag_load(Af[0], Bf[0], sb, 0, a_row_l, a_cb, b_row_l, b_cb);

    for (int s = 0; s < G; s++) {
        const uint32_t st = sb + (s % 3) * STAGE_BYTES;
        if (s + 2 < G) load_stage(s + 2, cta, tid, sb);
#pragma unroll
        for (int ks = 0; ks < 4; ks++) {
            const int cur = ks & 1, nxt = cur ^ 1;
            if (ks < 3) {
                frag_load(Af[nxt], Bf[nxt], st, (ks + 1) * 32,
                          a_row_l, a_cb, b_row_l, b_cb);
            } else if (s + 1 < G) {
                if (s + 2 < G)
                    asm volatile("cp.async.wait_group 1;" ::: "memory");
                else
                    asm volatile("cp.async.wait_group 0;" ::: "memory");
                __syncthreads();
                frag_load(Af[nxt], Bf[nxt], sb + ((s + 1) % 3) * STAGE_BYTES, 0,
                          a_row_l, a_cb, b_row_l, b_cb);
            }
            do_mma(acc, Af[cur], Bf[cur]);
        }

        if ((s & (KTPT - 1)) == KTPT - 1) {
            const int tile = cta + NCTA * (s >> 4);
            const int R = (tile >> 4) * BM;
            const int C = (tile & 15) * BNC;

            {
                float bl_[2][2], bd_[2][2], bb_[2][2];
#pragma unroll
                for (int g = 0; g < 2; g++)
#pragma unroll
                    for (int e = 0; e < 2; e++) {
                        const int gc = C + wn * 16 + g * 8 + q2 + e;
                        bl_[g][e] = __ldg(pbl + gc);
                        bd_[g][e] = __ldg(pbd + gc);
                        bb_[g][e] = __ldg(pbb + gc);
                    }
#pragma unroll
                for (int mt = 0; mt < 2; mt++)
#pragma unroll
                    for (int h = 0; h < 2; h++) {
                        const int row = wm * 32 + mt * 16 + (lane >> 2) + 8 * h;
#pragma unroll
                        for (int g = 0; g < 2; g++) {
                            float a0, a1, d0, d1;
#pragma unroll
                            for (int e = 0; e < 2; e++) {
                                float lam = softplus_f(acc[mt][g][2 * h + e]     + bl_[g][e]);
                                float de  = softplus_f(acc[mt][2 + g][2 * h + e] + bd_[g][e]);
                                float u   = acc[mt][4 + g][2 * h + e] + bb_[g][e];
                                float al  = __expf(-de * lam);
                                float dr  = de * u;
                                if (e == 0) { a0 = al; d0 = dr; } else { a1 = al; d1 = dr; }
                            }
                            const int ch = wn * 16 + g * 8 + q2;
                            *(float2*)&SA[row * ASTR + ch] = make_float2(a0, a1);
                            *(float2*)&SD[row * ASTR + ch] = make_float2(d0, d1);
                        }
                    }
            }
            __syncthreads();

            if (tid < 2 * BNC) {
                const int ch = tid & 63;
                const int hf = tid >> 6;
                float sc = 0.0f, P = 1.0f;
                const int t0 = hf * 64;
#pragma unroll 8
                for (int t = t0; t < t0 + 64; t++) {
                    float a = SA[t * ASTR + ch];
                    float d = SD[t * ASTR + ch];
                    sc = fmaf(a, sc, d);
                    P *= a;
                }
                sP[hf][ch] = P;
                sS[hf][ch] = sc;
            }
            __syncthreads();
            if (tid < BNC) {
                const float P = sP[0][tid] * sP[1][tid];
                const float sc = fmaf(sP[1][tid], sS[0][tid], sS[1][tid]);
                const int bidx = R >> 12;
                const int chunk = (R >> 7) & 31;
                const int idx = ((bidx * NCHUNK + chunk) << 10) + C + tid;
                g_P[idx] = P;
                g_S[idx] = sc;
            }

#pragma unroll
            for (int i = 0; i < 2; i++)
#pragma unroll
                for (int j = 0; j < 6; j++)
#pragma unroll
                    for (int k = 0; k < 4; k++) acc[i][j][k] = 0.0f;
            __syncthreads();
        }
    }
}

// ---------------- combine chunks + head projections ----------------
__global__ void __launch_bounds__(1024)
combine_kernel(const float* __restrict__ W_par, const float* __restrict__ b_par,
               const float* __restrict__ W_add, const float* __restrict__ b_add,
               float* __restrict__ out)
{
    const int b = blockIdx.x;
    const int d = threadIdx.x;

    float s = 0.0f;
#pragma unroll
    for (int c = 0; c < NCHUNK; c++) {
        const int idx = ((b * NCHUNK + c) << 10) + d;
        s = fmaf(g_P[idx], s, g_S[idx]);
    }

    float v0 = s * W_par[2 * d];
    float v1 = s * W_par[2 * d + 1];
    float v2 = s * W_add[d];

#pragma unroll
    for (int o = 16; o > 0; o >>= 1) {
        v0 += __shfl_xor_sync(0xffffffffu, v0, o);
        v1 += __shfl_xor_sync(0xffffffffu, v1, o);
        v2 += __shfl_xor_sync(0xffffffffu, v2, o);
    }

    __shared__ float r0[32], r1[32], r2[32];
    const int lane = d & 31, wid = d >> 5;
    if (lane == 0) { r0[wid] = v0; r1[wid] = v1; r2[wid] = v2; }
    __syncthreads();
    if (wid == 0) {
        v0 = r0[lane]; v1 = r1[lane]; v2 = r2[lane];
#pragma unroll
        for (int o = 16; o > 0; o >>= 1) {
            v0 += __shfl_xor_sync(0xffffffffu, v0, o);
            v1 += __shfl_xor_sync(0xffffffffu, v1, o);
            v2 += __shfl_xor_sync(0xffffffffu, v2, o);
        }
        if (lane == 0) {
            out[2 * b]     = v0 + b_par[0];
            out[2 * b + 1] = v1 + b_par[1];
            out[16 + b]    = v2 + b_add[0];
        }
    }
}

extern "C" void kernel_launch(void* const* d_in, const int* in_sizes, int n_in,
                              void* d_out, int out_size)
{
    const float* x  = (const float*)d_in[0];
    const float* Wl = (const float*)d_in[1];
    const float* bl = (const float*)d_in[2];
    const float* Wd = (const float*)d_in[3];
    const float* bd = (const float*)d_in[4];
    const float* Wb = (const float*)d_in[5];
    const float* bb = (const float*)d_in[6];
    const float* Wp = (const float*)d_in[7];
    const float* bp = (const float*)d_in[8];
    const float* Wa = (const float*)d_in[9];
    const float* ba = (const float*)d_in[10];
    float* out = (float*)d_out;

    cudaFuncSetAttribute(mamba_gemm_mma,
                         cudaFuncAttributeMaxDynamicSharedMemorySize, SMEM_TOTAL);

    prep_kernel<<<16384 + 3072, 256>>>(x, Wl, Wd, Wb);
    mamba_gemm_mma<<<NCTA, NTH, SMEM_TOTAL>>>(bl, bd, bb);
    combine_kernel<<<8, 1024>>>(Wp, bp, Wa, ba, out);
}

// round 16
// speedup vs baseline: 1.4156x; 1.0222x over previous
#include <cuda_runtime.h>
#include <cuda_fp16.h>
#include <stdint.h>
#include <math.h>

// ---------------------------------------------------------------------------
// SimpleMamba via warp-level mma.sync fp16 GEMM (single product).
//   R16 = R15 (543.1us) + epilogue-only micro-cuts:
//     - 4-way split scan (256 thr x 32 rows, serial fma chain halved)
//     - removed provably-redundant trailing __syncthreads per tile
//   Mainloop untouched (R10 plateau). Vectorized merged prep; 8us combine.
// ---------------------------------------------------------------------------

#define DM    1024
#define KD    1024
#define BM    128
#define BNC   64
#define BK    64
#define KTPT  16
#define NCHUNK 32
#define ASTR  66
#define NTILE 4096
#define NCTA  148

#define STAGE_BYTES 40960    // Ah 16K + Bh 24K
#define OFF_BH  16384
#define SCAN_OFF (3 * STAGE_BYTES)
#define SMEM_TOTAL (SCAN_OFF + 2 * BM * ASTR * 4)  // 190464

#define NTH 512

// ---------------- device scratch ----------------
__device__ __align__(128) __half g_Ah[32768u * 1024u];
__device__ __align__(128) __half g_Bh[3u * 1024u * 1024u];   // interleaved rows
__device__ float g_P[8 * NCHUNK * DM];
__device__ float g_S[8 * NCHUNK * DM];

// ---------------- helpers ----------------
static __device__ __forceinline__ uint32_t smem_u32(const void* p) {
    uint32_t a;
    asm("{ .reg .u64 t; cvta.to.shared.u64 t, %1; cvt.u32.u64 %0, t; }" : "=r"(a) : "l"(p));
    return a;
}
static __device__ __forceinline__ uint32_t sw128(uint32_t o) { return o ^ ((o >> 3) & 0x70); }

static __device__ __forceinline__ void cp16(uint32_t dst, const void* src) {
    asm volatile("cp.async.cg.shared.global [%0], [%1], 16;" :: "r"(dst), "l"(src) : "memory");
}
static __device__ __forceinline__ void ldsm4(uint32_t* r, uint32_t addr) {
    asm volatile("ldmatrix.sync.aligned.m8n8.x4.shared.b16 {%0,%1,%2,%3}, [%4];"
        : "=r"(r[0]), "=r"(r[1]), "=r"(r[2]), "=r"(r[3]) : "r"(addr));
}
static __device__ __forceinline__ void mma_f16(float* c, const uint32_t* a,
                                               uint32_t b0, uint32_t b1) {
    asm volatile("mma.sync.aligned.m16n8k16.row.col.f32.f16.f16.f32 "
        "{%0,%1,%2,%3}, {%4,%5,%6,%7}, {%8,%9}, {%0,%1,%2,%3};"
        : "+f"(c[0]), "+f"(c[1]), "+f"(c[2]), "+f"(c[3])
        : "r"(a[0]), "r"(a[1]), "r"(a[2]), "r"(a[3]), "r"(b0), "r"(b1));
}

static __device__ __forceinline__ float softplus_f(float z) {
    return fmaxf(z, 0.0f) + __logf(1.0f + __expf(-fabsf(z)));
}

// ---------------- merged prep kernel (vectorized) ----------------
__global__ void __launch_bounds__(256)
prep_kernel(const float* __restrict__ x, const float* __restrict__ Wl,
            const float* __restrict__ Wd, const float* __restrict__ Wb) {
    const int tid = threadIdx.x;
    if (blockIdx.x < 16384) {
        size_t i = (size_t)blockIdx.x * 256 + tid;   // 8-float group index
        float4 v0 = ((const float4*)x)[2 * i];
        float4 v1 = ((const float4*)x)[2 * i + 1];
        __half2 h[4];
        h[0] = __floats2half2_rn(v0.x, v0.y);
        h[1] = __floats2half2_rn(v0.z, v0.w);
        h[2] = __floats2half2_rn(v1.x, v1.y);
        h[3] = __floats2half2_rn(v1.z, v1.w);
        ((uint4*)g_Ah)[i] = *(const uint4*)h;
    } else {
        const int bid = blockIdx.x - 16384;        // 0..3071
        const int mat = bid >> 10;
        const int rem = bid & 1023;
        const int k0 = (rem >> 5) * 32;
        const int n0 = (rem & 31) * 32;
        const float* W = (mat == 0) ? Wl : (mat == 1) ? Wd : Wb;
        __shared__ float ts[32][33];
        const int tx = tid & 31, ty = tid >> 5;
#pragma unroll
        for (int i = 0; i < 4; i++) {
            int k = ty + i * 8;
            ts[k][tx] = W[(size_t)(k0 + k) * DM + n0 + tx];
        }
        __syncthreads();
#pragma unroll
        for (int i = 0; i < 4; i++) {
            int n = n0 + ty + i * 8;
            int row = (n >> 4) * 48 + mat * 16 + (n & 15);
            g_Bh[(size_t)row * KD + k0 + tx] = __float2half(ts[tx][ty + i * 8]);
        }
    }
}

// ---------------- GEMM + scan (persistent, R10 mainloop verbatim) ----------------
static __device__ __forceinline__ void load_stage(int s, int cta, int tid, uint32_t sb) {
    const int tile = cta + NCTA * (s >> 4);
    const int kt = s & 15;
    const int R = (tile >> 4) * BM;
    const int Crow = (tile & 15) * 192;
    const uint32_t st = sb + (s % 3) * STAGE_BYTES;
#pragma unroll
    for (int i = 0; i < 2; i++) {
        int c = i * NTH + tid;
        int row = c >> 3, q = c & 7;
        size_t g = ((size_t)(R + row) << 10) + kt * BK + q * 8;
        cp16(st + sw128((uint32_t)(row * 128 + q * 16)), g_Ah + g);
    }
#pragma unroll
    for (int i = 0; i < 3; i++) {
        int c = i * NTH + tid;
        int row = c >> 3, q = c & 7;
        size_t g = ((size_t)(Crow + row) << 10) + kt * BK + q * 8;
        cp16(st + OFF_BH + sw128((uint32_t)(row * 128 + q * 16)), g_Bh + g);
    }
    asm volatile("cp.async.commit_group;" ::: "memory");
}

static __device__ __forceinline__ void frag_load(uint32_t A[2][4], uint32_t B[3][4],
                                                 uint32_t st, int kb,
                                                 int a_row_l, int a_cb,
                                                 int b_row_l, int b_cb) {
#pragma unroll
    for (int mt = 0; mt < 2; mt++)
        ldsm4(A[mt], st + sw128((uint32_t)((a_row_l + mt * 16) * 128 + kb + a_cb)));
#pragma unroll
    for (int nt = 0; nt < 3; nt++)
        ldsm4(B[nt], st + OFF_BH + sw128((uint32_t)((b_row_l + nt * 16) * 128 + kb + b_cb)));
}

static __device__ __forceinline__ void do_mma(float acc[2][6][4],
                                              uint32_t A[2][4], uint32_t B[3][4]) {
#pragma unroll
    for (int mt = 0; mt < 2; mt++)
#pragma unroll
        for (int nt = 0; nt < 3; nt++) {
            mma_f16(acc[mt][2 * nt],     A[mt], B[nt][0], B[nt][1]);
            mma_f16(acc[mt][2 * nt + 1], A[mt], B[nt][2], B[nt][3]);
        }
}

__global__ void __launch_bounds__(NTH)
mamba_gemm_mma(const float* __restrict__ pbl, const float* __restrict__ pbd,
               const float* __restrict__ pbb) {
    extern __shared__ char smem[];
    const uint32_t sb = smem_u32(smem);
    const int tid = threadIdx.x;
    const int warp = tid >> 5;
    const int lane = tid & 31;
    const int cta = blockIdx.x;
    const int wm = warp >> 2;
    const int wn = warp & 3;

    const int ntiles = (NTILE - cta + NCTA - 1) / NCTA;
    const int G = ntiles * KTPT;

    float* SA = (float*)(smem + SCAN_OFF);
    float* SD = SA + BM * ASTR;
    __shared__ float sP[4][BNC], sS[4][BNC];

    float acc[2][6][4];
#pragma unroll
    for (int i = 0; i < 2; i++)
#pragma unroll
        for (int j = 0; j < 6; j++)
#pragma unroll
            for (int k = 0; k < 4; k++) acc[i][j][k] = 0.0f;

    const int a_row_l = wm * 32 + (lane & 15);
    const int a_cb = (lane >> 4) * 16;
    const int b_row_l = wn * 48 + ((lane >> 4) & 1) * 8 + (lane & 7);
    const int b_cb = ((lane >> 3) & 1) * 16;
    const int q2 = 2 * (lane & 3);

    uint32_t Af[2][2][4], Bf[2][3][4];

    load_stage(0, cta, tid, sb);
    load_stage(1, cta, tid, sb);
    asm volatile("cp.async.wait_group 1;" ::: "memory");
    __syncthreads();
    frag_load(Af[0], Bf[0], sb, 0, a_row_l, a_cb, b_row_l, b_cb);

    for (int s = 0; s < G; s++) {
        const uint32_t st = sb + (s % 3) * STAGE_BYTES;
        if (s + 2 < G) load_stage(s + 2, cta, tid, sb);
#pragma unroll
        for (int ks = 0; ks < 4; ks++) {
            const int cur = ks & 1, nxt = cur ^ 1;
            if (ks < 3) {
                frag_load(Af[nxt], Bf[nxt], st, (ks + 1) * 32,
                          a_row_l, a_cb, b_row_l, b_cb);
            } else if (s + 1 < G) {
                if (s + 2 < G)
                    asm volatile("cp.async.wait_group 1;" ::: "memory");
                else
                    asm volatile("cp.async.wait_group 0;" ::: "memory");
                __syncthreads();
                frag_load(Af[nxt], Bf[nxt], sb + ((s + 1) % 3) * STAGE_BYTES, 0,
                          a_row_l, a_cb, b_row_l, b_cb);
            }
            do_mma(acc, Af[cur], Bf[cur]);
        }

        if ((s & (KTPT - 1)) == KTPT - 1) {
            const int tile = cta + NCTA * (s >> 4);
            const int R = (tile >> 4) * BM;
            const int C = (tile & 15) * BNC;

            {
                float bl_[2][2], bd_[2][2], bb_[2][2];
#pragma unroll
                for (int g = 0; g < 2; g++)
#pragma unroll
                    for (int e = 0; e < 2; e++) {
                        const int gc = C + wn * 16 + g * 8 + q2 + e;
                        bl_[g][e] = __ldg(pbl + gc);
                        bd_[g][e] = __ldg(pbd + gc);
                        bb_[g][e] = __ldg(pbb + gc);
                    }
#pragma unroll
                for (int mt = 0; mt < 2; mt++)
#pragma unroll
                    for (int h = 0; h < 2; h++) {
                        const int row = wm * 32 + mt * 16 + (lane >> 2) + 8 * h;
#pragma unroll
                        for (int g = 0; g < 2; g++) {
                            float a0, a1, d0, d1;
#pragma unroll
                            for (int e = 0; e < 2; e++) {
                                float lam = softplus_f(acc[mt][g][2 * h + e]     + bl_[g][e]);
                                float de  = softplus_f(acc[mt][2 + g][2 * h + e] + bd_[g][e]);
                                float u   = acc[mt][4 + g][2 * h + e] + bb_[g][e];
                                float al  = __expf(-de * lam);
                                float dr  = de * u;
                                if (e == 0) { a0 = al; d0 = dr; } else { a1 = al; d1 = dr; }
                            }
                            const int ch = wn * 16 + g * 8 + q2;
                            *(float2*)&SA[row * ASTR + ch] = make_float2(a0, a1);
                            *(float2*)&SD[row * ASTR + ch] = make_float2(d0, d1);
                        }
                    }
            }
            __syncthreads();

            // ---- 4-way split scan: 256 threads, 32 rows each ----
            if (tid < 4 * BNC) {
                const int ch = tid & 63;
                const int qu = tid >> 6;       // 0..3
                float sc = 0.0f, P = 1.0f;
                const int t0 = qu * 32;
#pragma unroll 8
                for (int t = t0; t < t0 + 32; t++) {
                    float a = SA[t * ASTR + ch];
                    float d = SD[t * ASTR + ch];
                    sc = fmaf(a, sc, d);
                    P *= a;
                }
                sP[qu][ch] = P;
                sS[qu][ch] = sc;
            }
            __syncthreads();
            if (tid < BNC) {
                float P = sP[0][tid];
                float sc = sS[0][tid];
#pragma unroll
                for (int qu = 1; qu < 4; qu++) {
                    sc = fmaf(sP[qu][tid], sc, sS[qu][tid]);
                    P *= sP[qu][tid];
                }
                const int bidx = R >> 12;
                const int chunk = (R >> 7) & 31;
                const int idx = ((bidx * NCHUNK + chunk) << 10) + C + tid;
                g_P[idx] = P;
                g_S[idx] = sc;
            }

            // no trailing __syncthreads: next SA/SD write is 16 stages away,
            // with a barrier at every stage boundary in between.
#pragma unroll
            for (int i = 0; i < 2; i++)
#pragma unroll
                for (int j = 0; j < 6; j++)
#pragma unroll
                    for (int k = 0; k < 4; k++) acc[i][j][k] = 0.0f;
        }
    }
}

// ---------------- combine chunks + head projections ----------------
__global__ void __launch_bounds__(1024)
combine_kernel(const float* __restrict__ W_par, const float* __restrict__ b_par,
               const float* __restrict__ W_add, const float* __restrict__ b_add,
               float* __restrict__ out)
{
    const int b = blockIdx.x;
    const int d = threadIdx.x;

    float s = 0.0f;
#pragma unroll
    for (int c = 0; c < NCHUNK; c++) {
        const int idx = ((b * NCHUNK + c) << 10) + d;
        s = fmaf(g_P[idx], s, g_S[idx]);
    }

    float v0 = s * W_par[2 * d];
    float v1 = s * W_par[2 * d + 1];
    float v2 = s * W_add[d];

#pragma unroll
    for (int o = 16; o > 0; o >>= 1) {
        v0 += __shfl_xor_sync(0xffffffffu, v0, o);
        v1 += __shfl_xor_sync(0xffffffffu, v1, o);
        v2 += __shfl_xor_sync(0xffffffffu, v2, o);
    }

    __shared__ float r0[32], r1[32], r2[32];
    const int lane = d & 31, wid = d >> 5;
    if (lane == 0) { r0[wid] = v0; r1[wid] = v1; r2[wid] = v2; }
    __syncthreads();
    if (wid == 0) {
        v0 = r0[lane]; v1 = r1[lane]; v2 = r2[lane];
#pragma unroll
        for (int o = 16; o > 0; o >>= 1) {
            v0 += __shfl_xor_sync(0xffffffffu, v0, o);
            v1 += __shfl_xor_sync(0xffffffffu, v1, o);
            v2 += __shfl_xor_sync(0xffffffffu, v2, o);
        }
        if (lane == 0) {
            out[2 * b]     = v0 + b_par[0];
            out[2 * b + 1] = v1 + b_par[1];
            out[16 + b]    = v2 + b_add[0];
        }
    }
}

extern "C" void kernel_launch(void* const* d_in, const int* in_sizes, int n_in,
                              void* d_out, int out_size)
{
    const float* x  = (const float*)d_in[0];
    const float* Wl = (const float*)d_in[1];
    const float* bl = (const float*)d_in[2];
    const float* Wd = (const float*)d_in[3];
    const float* bd = (const float*)d_in[4];
    const float* Wb = (const float*)d_in[5];
    const float* bb = (const float*)d_in[6];
    const float* Wp = (const float*)d_in[7];
    const float* bp = (const float*)d_in[8];
    const float* Wa = (const float*)d_in[9];
    const float* ba = (const float*)d_in[10];
    float* out = (float*)d_out;

    cudaFuncSetAttribute(mamba_gemm_mma,
                         cudaFuncAttributeMaxDynamicSharedMemorySize, SMEM_TOTAL);

    prep_kernel<<<16384 + 3072, 256>>>(x, Wl, Wd, Wb);
    mamba_gemm_mma<<<NCTA, NTH, SMEM_TOTAL>>>(bl, bd, bb);
    combine_kernel<<<8, 1024>>>(Wp, bp, Wa, ba, out);
}